// round 15
// baseline (speedup 1.0000x reference)
#include <cuda_runtime.h>
#include <math.h>

#define VG  19
#define NN  608
#define LS  256
#define ROW 38912   /* 608*64 */
#define BCR 9728    /* 608*16 */
#define YPG 9961472 /* 256*608*64 */
#define NTH 608

typedef unsigned long long ull;

__device__ __align__(16) float g_deg[NN];            // zero-init; re-zeroed by k_post
__device__ __align__(16) float g_Nm[32 * 361];
__device__ __align__(16) float g_dt[LS * NN * 64];
__device__ __align__(16) float g_u [LS * NN * 64];
__device__ __align__(16) float g_z [LS * NN * 64];
__device__ __align__(16) float g_B [LS * NN * 16];
__device__ __align__(16) float g_C [LS * NN * 16];
__device__ __align__(16) float g_G [LS * NN * 64];
__device__ __align__(16) float g_yp[4 * YPG];

__device__ __forceinline__ float softplusf(float x) {
    return x > 20.f ? x : log1pf(expf(x));
}
__device__ __forceinline__ ull fma2(ull a, ull b, ull c) {
    ull d;
    asm("fma.rn.f32x2 %0, %1, %2, %3;" : "=l"(d) : "l"(a), "l"(b), "l"(c));
    return d;
}
__device__ __forceinline__ float lo2(ull a) { float l, h; asm("mov.b64 {%0,%1}, %2;" : "=f"(l), "=f"(h) : "l"(a)); return l; }
__device__ __forceinline__ float hi2(ull a) { float l, h; asm("mov.b64 {%0,%1}, %2;" : "=f"(l), "=f"(h) : "l"(a)); return h; }
__device__ __forceinline__ ull pk2(float l, float h) { ull r; asm("mov.b64 %0, {%1,%2};" : "=l"(r) : "f"(l), "f"(h)); return r; }

// ---------- launch 1: degree ----------
__global__ void k_deg(const int* __restrict__ ei, const float* __restrict__ ew, int E) {
    int i = blockIdx.x * blockDim.x + threadIdx.x;
    if (i < E)           atomicAdd(&g_deg[ei[E + i]], ew[i]);
    else if (i < E + NN) atomicAdd(&g_deg[i - E], 1.f);
}

// ---------- launch 2: normalized adjacency ----------
__global__ void k_nmat(const int* __restrict__ ei, const float* __restrict__ ew, int E) {
    int i = blockIdx.x * blockDim.x + threadIdx.x;
    if (i < E) {
        int s = ei[i], d = ei[E + i];
        float nm = ew[i] * rsqrtf(fmaxf(g_deg[s], 1e-12f)) * rsqrtf(fmaxf(g_deg[d], 1e-12f));
        int bb = d / VG;
        g_Nm[bb * 361 + (d - bb * VG) * VG + (s - bb * VG)] = nm;
    } else if (i < E + NN) {
        int vv = i - E;
        float r = rsqrtf(fmaxf(g_deg[vv], 1e-12f));
        g_Nm[(vv / VG) * 361 + (vv % VG) * VG + (vv % VG)] = r * r;
    }
}

// ---------- launch 3: fused projections + ub precompute, block per (t,b) ----------
__global__ void __launch_bounds__(NTH) k_preub(
    const float* __restrict__ x_in, const float* __restrict__ ipw,
    const float* __restrict__ xpw,  const float* __restrict__ dtw,
    const float* __restrict__ dtb,  const float* __restrict__ gBw,
    const float* __restrict__ gBb)
{
    __shared__ __align__(16) float wsh[4096];
    __shared__ __align__(16) float xs[608];
    __shared__ __align__(16) float us[1216];
    __shared__ __align__(16) float uaS[1216];
    __shared__ __align__(16) float xpws[2304];
    __shared__ __align__(16) float bBs[64];
    __shared__ __align__(16) float dtr[40];
    __shared__ __align__(16) float nm[364];

    int tb = blockIdx.x, t = tb >> 5, b = tb & 31;
    int tid = threadIdx.x;
    int v = tid >> 5, l = tid & 31;

    for (int i = tid; i < 4096; i += NTH) wsh[(i & 31) * 128 + (i >> 5)] = ipw[i];
    { int node = b * VG + v; xs[tid] = x_in[node * 8192 + t * 32 + l]; }
    for (int i = tid; i < 2176; i += NTH) { int j = i >> 6, d = i & 63; xpws[d * 36 + j] = xpw[i]; }
    for (int i = tid; i < 361; i += NTH) nm[i] = g_Nm[b * 361 + i];
    if (tid < 64) bBs[tid] = gBb[tid];
    __syncthreads();

    float u0 = 0, u1 = 0, z0 = 0, z1 = 0;
    #pragma unroll 8
    for (int k = 0; k < 32; ++k) {
        float xk = xs[v * 32 + k];
        u0 = fmaf(wsh[k * 128 + l], xk, u0);
        u1 = fmaf(wsh[k * 128 + 32 + l], xk, u1);
        z0 = fmaf(wsh[k * 128 + 64 + l], xk, z0);
        z1 = fmaf(wsh[k * 128 + 96 + l], xk, z1);
    }
    us[v * 64 + l] = u0; us[v * 64 + 32 + l] = u1;
    int gb = t * ROW + (b * VG + v) * 64;
    g_u[gb + l] = u0; g_u[gb + 32 + l] = u1;
    g_z[gb + l] = z0; g_z[gb + 32 + l] = z1;
    __syncthreads();

    for (int idx = tid; idx < 646; idx += NTH) {
        int vv = idx / 34, j = idx - vv * 34;
        float a = 0.f;
        #pragma unroll 8
        for (int d = 0; d < 64; ++d) a = fmaf(xpws[d * 36 + j], us[vv * 64 + d], a);
        if (j < 2)       dtr[vv * 2 + j] = a;
        else if (j < 18) g_B[t * BCR + (b * VG + vv) * 16 + (j - 2)] = a;
        else             g_C[t * BCR + (b * VG + vv) * 16 + (j - 18)] = a;
    }
    for (int i = tid; i < 4096; i += NTH) wsh[(i & 63) * 64 + (i >> 6)] = gBw[i];
    __syncthreads();

    float r0 = dtr[v * 2], r1 = dtr[v * 2 + 1];
    float d0 = softplusf(fmaf(r0, dtw[l * 2], fmaf(r1, dtw[l * 2 + 1], dtb[l])));
    float d1 = softplusf(fmaf(r0, dtw[(l + 32) * 2], fmaf(r1, dtw[(l + 32) * 2 + 1], dtb[l + 32])));
    g_dt[gb + l] = d0; g_dt[gb + 32 + l] = d1;

    float a0 = 0, a1 = 0;
    #pragma unroll
    for (int vp = 0; vp < VG; ++vp) {
        float n = nm[v * VG + vp];
        a0 = fmaf(n, us[vp * 64 + l], a0);
        a1 = fmaf(n, us[vp * 64 + 32 + l], a1);
    }
    uaS[v * 64 + l] = a0; uaS[v * 64 + 32 + l] = a1;
    __syncthreads();

    float gg0 = bBs[l], gg1 = bBs[l + 32];
    #pragma unroll 8
    for (int k = 0; k < 64; ++k) {
        float ua0 = uaS[v * 64 + k];
        gg0 = fmaf(wsh[k * 64 + l], ua0, gg0);
        gg1 = fmaf(wsh[k * 64 + 32 + l], ua0, gg1);
    }
    g_G[gb + l] = gg0 * d0; g_G[gb + 32 + l] = gg1 * d1;
}

// ---------- launch 4: scan, persistent, 128 CTAs ----------
// smem float offsets (all 16B aligned)
#define O_WA    0       /* 4096: WAe[k*64+e] */
#define O_WC    4096    /* 4096 */
#define O_NMTD  8192    /* 768: dup nm pairs [vp][vq][8] */
#define O_S     8960    /* 4864: S4[(v<<6)+e] float4 over n */
#define O_QD01  13824   /* 4864: dup Q (n0,n0,n1,n1) at [(v*64+k)*4] */
#define O_QD23  18688   /* 4864 */
#define O_QCD   23552   /* 2432: dup QC at [(v*64+k)*2] */
#define O_DT    25984   /* 1216 */
#define O_G2    27200   /* 1216 */
#define O_BS    28416   /* 160 */
#define O_CS    28576   /* 160 */
#define O_CSV   28736   /* 32 */
#define SMTOT   28768

__global__ void __launch_bounds__(NTH, 1) k_scan(
    const float* __restrict__ A_log,
    const float* __restrict__ gAw, const float* __restrict__ gAb,
    const float* __restrict__ gCw, const float* __restrict__ gCb)
{
    extern __shared__ __align__(16) float sm[];
    float* WAe  = sm + O_WA;
    float* WCe  = sm + O_WC;
    float* NMTD = sm + O_NMTD;
    float* QD01 = sm + O_QD01;
    float* QD23 = sm + O_QD23;
    float* QCD  = sm + O_QCD;
    float* CSVs = sm + O_CSV;
    float4* S4   = (float4*)(sm + O_S);
    float4* dts4 = (float4*)(sm + O_DT);
    float4* Gs4  = (float4*)(sm + O_G2);
    float4* BSb  = (float4*)(sm + O_BS);
    float4* CSb  = (float4*)(sm + O_CS);

    const int tid = threadIdx.x;
    const int b = blockIdx.x >> 2, g = blockIdx.x & 3;

    for (int i = tid; i < 4096; i += NTH) {
        WAe[i] = gAw[(i & 63) * 64 + (i >> 6)];
        WCe[i] = gCw[(i & 63) * 64 + (i >> 6)];
    }
    for (int i = tid; i < 760; i += NTH) {
        int vp = i / 40, rem = i % 40, vq = rem >> 3, j = rem & 7;
        int vv = vq * 4 + (j >> 1);
        NMTD[i] = (vv < VG) ? g_Nm[b * 361 + vv * VG + vp] : 0.f;
    }

    // phase-2 role mapping
    const int tv = (tid < 304) ? (tid >> 4) : ((tid - 304) >> 4);
    const int eq = (tid < 304) ? (tid & 15) : ((tid - 304) & 15);

    float A00,A01,A02,A03, A10,A11,A12,A13, A20,A21,A22,A23, A30,A31,A32,A33;
    float bA0, bA1, bA2, bA3;
    float4 bc;
    if (tid < 304) {
        int e = eq * 4;
        A00 = -__expf(A_log[(e+0)*16 + g*4+0]); A01 = -__expf(A_log[(e+0)*16 + g*4+1]);
        A02 = -__expf(A_log[(e+0)*16 + g*4+2]); A03 = -__expf(A_log[(e+0)*16 + g*4+3]);
        A10 = -__expf(A_log[(e+1)*16 + g*4+0]); A11 = -__expf(A_log[(e+1)*16 + g*4+1]);
        A12 = -__expf(A_log[(e+1)*16 + g*4+2]); A13 = -__expf(A_log[(e+1)*16 + g*4+3]);
        A20 = -__expf(A_log[(e+2)*16 + g*4+0]); A21 = -__expf(A_log[(e+2)*16 + g*4+1]);
        A22 = -__expf(A_log[(e+2)*16 + g*4+2]); A23 = -__expf(A_log[(e+2)*16 + g*4+3]);
        A30 = -__expf(A_log[(e+3)*16 + g*4+0]); A31 = -__expf(A_log[(e+3)*16 + g*4+1]);
        A32 = -__expf(A_log[(e+3)*16 + g*4+2]); A33 = -__expf(A_log[(e+3)*16 + g*4+3]);
        bA0 = gAb[e]; bA1 = gAb[e+1]; bA2 = gAb[e+2]; bA3 = gAb[e+3];
    } else {
        int e = eq * 4;
        bc = make_float4(gCb[e], gCb[e+1], gCb[e+2], gCb[e+3]);
    }

    // prologue: S = s_new(0); stage C(0) into parity 0
    if (tid < 304) {
        const float4* gdt4 = (const float4*)(g_dt + b * 1216);
        const float4* gG4  = (const float4*)(g_G  + b * 1216);
        float4 dt0 = gdt4[tv * 16 + eq];
        float4 G0  = gG4 [tv * 16 + eq];
        float4 B0  = *(const float4*)&g_B[(b * VG + tv) * 16 + g * 4];
        float4 s;
        s.x = fmaf(bA0, __expf(dt0.x * A00), G0.x * B0.x);
        s.y = fmaf(bA0, __expf(dt0.x * A01), G0.x * B0.y);
        s.z = fmaf(bA0, __expf(dt0.x * A02), G0.x * B0.z);
        s.w = fmaf(bA0, __expf(dt0.x * A03), G0.x * B0.w);
        S4[(tv << 6) + (eq << 2) + 0] = s;
        s.x = fmaf(bA1, __expf(dt0.y * A10), G0.y * B0.x);
        s.y = fmaf(bA1, __expf(dt0.y * A11), G0.y * B0.y);
        s.z = fmaf(bA1, __expf(dt0.y * A12), G0.y * B0.z);
        s.w = fmaf(bA1, __expf(dt0.y * A13), G0.y * B0.w);
        S4[(tv << 6) + (eq << 2) + 1] = s;
        s.x = fmaf(bA2, __expf(dt0.z * A20), G0.z * B0.x);
        s.y = fmaf(bA2, __expf(dt0.z * A21), G0.z * B0.y);
        s.z = fmaf(bA2, __expf(dt0.z * A22), G0.z * B0.z);
        s.w = fmaf(bA2, __expf(dt0.z * A23), G0.z * B0.w);
        S4[(tv << 6) + (eq << 2) + 2] = s;
        s.x = fmaf(bA3, __expf(dt0.w * A30), G0.w * B0.x);
        s.y = fmaf(bA3, __expf(dt0.w * A31), G0.w * B0.y);
        s.z = fmaf(bA3, __expf(dt0.w * A32), G0.w * B0.z);
        s.w = fmaf(bA3, __expf(dt0.w * A33), G0.w * B0.w);
        S4[(tv << 6) + (eq << 2) + 3] = s;
    } else {
        int j0 = tid - 304;
        if (j0 < VG) CSb[j0] = *(const float4*)&g_C[(b * VG + j0) * 16 + g * 4];
    }
    float* yout = g_yp + (size_t)g * YPG;
    __syncthreads();

    for (int t = 0; t < LS; ++t) {
        const int cur = t & 1, nxt = (t + 1) & 1;
        // ---- Phase 1: Agg (tid<320, f32x2) + prefetch t+1 (tid>=320) ----
        if (tid < 320) {
            int vq = tid >> 6, ae = tid & 63;
            ull q01[4] = {0,0,0,0}, q23[4] = {0,0,0,0};
            #pragma unroll
            for (int vp = 0; vp < VG; ++vp) {
                ulonglong2 sv  = *(const ulonglong2*)(sm + O_S + (((vp << 6) + ae) << 2));
                ulonglong2 n01 = *(const ulonglong2*)(NMTD + (vp * 5 + vq) * 8);
                ulonglong2 n23 = *(const ulonglong2*)(NMTD + (vp * 5 + vq) * 8 + 4);
                q01[0] = fma2(n01.x, sv.x, q01[0]); q23[0] = fma2(n01.x, sv.y, q23[0]);
                q01[1] = fma2(n01.y, sv.x, q01[1]); q23[1] = fma2(n01.y, sv.y, q23[1]);
                q01[2] = fma2(n23.x, sv.x, q01[2]); q23[2] = fma2(n23.x, sv.y, q23[2]);
                q01[3] = fma2(n23.y, sv.x, q01[3]); q23[3] = fma2(n23.y, sv.y, q23[3]);
            }
            int nj = (vq < 4) ? 4 : 3;
            #pragma unroll
            for (int j = 0; j < 4; ++j) {
                if (j >= nj) break;
                int vv = vq * 4 + j;
                float f0 = lo2(q01[j]), f1 = hi2(q01[j]);
                float f2 = lo2(q23[j]), f3 = hi2(q23[j]);
                int base = ((vv << 6) + ae) << 2;
                *(float4*)(QD01 + base) = make_float4(f0, f0, f1, f1);
                *(float4*)(QD23 + base) = make_float4(f2, f2, f3, f3);
                float4 c = CSb[cur * 20 + vv];
                float qc = f0 * c.x + f1 * c.y + f2 * c.z + f3 * c.w;
                *(ull*)(QCD + (((vv << 6) + ae) << 1)) = pk2(qc, qc);
            }
        } else {
            int j0 = tid - 320;   // 0..287
            int tn = (t + 1 < LS) ? t + 1 : t;
            const float4* gdt4 = (const float4*)(g_dt + tn * ROW + b * 1216);
            const float4* gG4  = (const float4*)(g_G  + tn * ROW + b * 1216);
            for (int idx = j0; idx < 304; idx += 288) {
                dts4[idx] = gdt4[idx];
                Gs4[idx]  = gG4[idx];
            }
            if (j0 < VG) {
                BSb[nxt * 20 + j0] = *(const float4*)&g_B[tn * BCR + (b * VG + j0) * 16 + g * 4];
            } else if (j0 >= 32 && j0 < 32 + VG) {
                int vv = j0 - 32;
                CSb[nxt * 20 + vv] = *(const float4*)&g_C[tn * BCR + (b * VG + vv) * 16 + g * 4];
            } else if (j0 >= 64 && j0 < 64 + VG) {
                int vv = j0 - 64;
                float4 cc = CSb[cur * 20 + vv];
                CSVs[vv] = cc.x + cc.y + cc.z + cc.w;
            }
        }
        __syncthreads();

        // ---- Phase 2: R-GEMM (f32x2) + fused E -> S(t+1)  ||  y-GEMM (f32x2) ----
        if (tid < 304) {
            ull e01n0 = 0, e01n1 = 0, e01n2 = 0, e01n3 = 0;
            ull e23n0 = 0, e23n1 = 0, e23n2 = 0, e23n3 = 0;
            #pragma unroll 8
            for (int k = 0; k < 64; ++k) {
                ulonglong2 wv = *(const ulonglong2*)(WAe + ((k << 6) + (eq << 2)));
                ulonglong2 qa = *(const ulonglong2*)(QD01 + (((tv << 6) + k) << 2));
                ulonglong2 qb = *(const ulonglong2*)(QD23 + (((tv << 6) + k) << 2));
                e01n0 = fma2(wv.x, qa.x, e01n0); e01n1 = fma2(wv.x, qa.y, e01n1);
                e01n2 = fma2(wv.x, qb.x, e01n2); e01n3 = fma2(wv.x, qb.y, e01n3);
                e23n0 = fma2(wv.y, qa.x, e23n0); e23n1 = fma2(wv.y, qa.y, e23n1);
                e23n2 = fma2(wv.y, qb.x, e23n2); e23n3 = fma2(wv.y, qb.y, e23n3);
            }
            // unpack to per-e float4 over n
            float4 a0 = make_float4(lo2(e01n0), lo2(e01n1), lo2(e01n2), lo2(e01n3));
            float4 a1 = make_float4(hi2(e01n0), hi2(e01n1), hi2(e01n2), hi2(e01n3));
            float4 a2 = make_float4(lo2(e23n0), lo2(e23n1), lo2(e23n2), lo2(e23n3));
            float4 a3 = make_float4(hi2(e23n0), hi2(e23n1), hi2(e23n2), hi2(e23n3));
            // fused E: S(t+1) = (R + bA)*exp(dt*A) + G*B   (dt/G/B are t+1 data)
            float4 dt4 = dts4[tv * 16 + eq];
            float4 g4  = Gs4 [tv * 16 + eq];
            float4 b4  = BSb[nxt * 20 + tv];
            float4 s;
            s.x = fmaf(a0.x + bA0, __expf(dt4.x * A00), g4.x * b4.x);
            s.y = fmaf(a0.y + bA0, __expf(dt4.x * A01), g4.x * b4.y);
            s.z = fmaf(a0.z + bA0, __expf(dt4.x * A02), g4.x * b4.z);
            s.w = fmaf(a0.w + bA0, __expf(dt4.x * A03), g4.x * b4.w);
            S4[(tv << 6) + (eq << 2) + 0] = s;
            s.x = fmaf(a1.x + bA1, __expf(dt4.y * A10), g4.y * b4.x);
            s.y = fmaf(a1.y + bA1, __expf(dt4.y * A11), g4.y * b4.y);
            s.z = fmaf(a1.z + bA1, __expf(dt4.y * A12), g4.y * b4.z);
            s.w = fmaf(a1.w + bA1, __expf(dt4.y * A13), g4.y * b4.w);
            S4[(tv << 6) + (eq << 2) + 1] = s;
            s.x = fmaf(a2.x + bA2, __expf(dt4.z * A20), g4.z * b4.x);
            s.y = fmaf(a2.y + bA2, __expf(dt4.z * A21), g4.z * b4.y);
            s.z = fmaf(a2.z + bA2, __expf(dt4.z * A22), g4.z * b4.z);
            s.w = fmaf(a2.w + bA2, __expf(dt4.z * A23), g4.z * b4.w);
            S4[(tv << 6) + (eq << 2) + 2] = s;
            s.x = fmaf(a3.x + bA3, __expf(dt4.w * A30), g4.w * b4.x);
            s.y = fmaf(a3.y + bA3, __expf(dt4.w * A31), g4.w * b4.y);
            s.z = fmaf(a3.z + bA3, __expf(dt4.w * A32), g4.w * b4.z);
            s.w = fmaf(a3.w + bA3, __expf(dt4.w * A33), g4.w * b4.w);
            S4[(tv << 6) + (eq << 2) + 3] = s;
        } else {
            float csv = CSVs[tv];
            ull acc01 = pk2(bc.x * csv, bc.y * csv);
            ull acc23 = pk2(bc.z * csv, bc.w * csv);
            #pragma unroll 8
            for (int k = 0; k < 64; ++k) {
                ulonglong2 wv = *(const ulonglong2*)(WCe + ((k << 6) + (eq << 2)));
                ull qc = *(const ull*)(QCD + (((tv << 6) + k) << 1));
                acc01 = fma2(wv.x, qc, acc01);
                acc23 = fma2(wv.y, qc, acc23);
            }
            float4 acc = make_float4(lo2(acc01), hi2(acc01), lo2(acc23), hi2(acc23));
            *(float4*)(yout + (size_t)t * ROW + (b * VG + tv) * 64 + (eq << 2)) = acc;
        }
        __syncthreads();
    }
}

// ---------- launch 5: post + deg re-zero ----------
__global__ void __launch_bounds__(256) k_post(
    const float* __restrict__ Dp, const float* __restrict__ opw, float* __restrict__ out)
{
    __shared__ float ys[256];
    int tid = threadIdx.x;
    if (blockIdx.x < 3) { int i = blockIdx.x * 256 + tid; if (i < NN) g_deg[i] = 0.f; }
    int sub = tid >> 6, e = tid & 63;
    int pos = blockIdx.x * 4 + sub;
    int node = pos >> 8, t = pos & 255;
    int ib = t * ROW + node * 64 + e;
    float y = g_yp[ib] + g_yp[YPG + ib] + g_yp[2 * YPG + ib] + g_yp[3 * YPG + ib];
    y = fmaf(Dp[e], g_u[ib], y);
    float z = g_z[ib];
    y *= z / (1.f + expf(-z));
    ys[sub * 64 + e] = y;
    __syncthreads();
    if (e < 32) {
        float a = 0.f;
        #pragma unroll 8
        for (int k = 0; k < 64; ++k) a = fmaf(opw[e * 64 + k], ys[sub * 64 + k], a);
        out[pos * 32 + e] = a;
    }
}

extern "C" void kernel_launch(void* const* d_in, const int* in_sizes, int n_in,
                              void* d_out, int out_size) {
    const float* x_in = (const float*)d_in[0];
    const int*   ei   = (const int*)  d_in[1];
    const float* ew   = (const float*)d_in[2];
    const float* ipw  = (const float*)d_in[3];
    const float* xpw  = (const float*)d_in[4];
    const float* dtw  = (const float*)d_in[5];
    const float* dtb  = (const float*)d_in[6];
    const float* Alog = (const float*)d_in[7];
    const float* Dp   = (const float*)d_in[8];
    const float* opw  = (const float*)d_in[9];
    const float* gAw  = (const float*)d_in[10];
    const float* gAb  = (const float*)d_in[11];
    const float* gBw  = (const float*)d_in[12];
    const float* gBb  = (const float*)d_in[13];
    const float* gCw  = (const float*)d_in[14];
    const float* gCb  = (const float*)d_in[15];
    float* out = (float*)d_out;
    int E = in_sizes[1] / 2;

    static int smem_set = 0;
    if (!smem_set) {
        cudaFuncSetAttribute(k_scan, cudaFuncAttributeMaxDynamicSharedMemorySize, SMTOT * 4);
        smem_set = 1;
    }

    k_deg  <<<(E + NN + 255) / 256, 256>>>(ei, ew, E);
    k_nmat <<<(E + NN + 255) / 256, 256>>>(ei, ew, E);
    k_preub<<<LS * 32, NTH>>>(x_in, ipw, xpw, dtw, dtb, gBw, gBb);
    k_scan <<<128, NTH, SMTOT * 4>>>(Alog, gAw, gAb, gCw, gCb);
    k_post <<<NN * LS / 4, 256>>>(Dp, opw, out);
}

// round 16
// speedup vs baseline: 1.7234x; 1.7234x over previous
#include <cuda_runtime.h>
#include <math.h>

#define VG  19
#define NN  608
#define LS  256
#define ROW 38912   /* 608*64 */
#define BCR 9728    /* 608*16 */
#define YPG 9961472 /* 256*608*64 */
#define NTH 608

__device__ __align__(16) float g_deg[NN];            // zero-init; re-zeroed by k_post
__device__ __align__(16) float g_Nm[32 * 361];
__device__ __align__(16) float g_dt[LS * NN * 64];
__device__ __align__(16) float g_u [LS * NN * 64];
__device__ __align__(16) float g_z [LS * NN * 64];
__device__ __align__(16) float g_B [LS * NN * 16];
__device__ __align__(16) float g_C [LS * NN * 16];
__device__ __align__(16) float g_G [LS * NN * 64];
__device__ __align__(16) float g_yp[4 * YPG];

__device__ __forceinline__ float softplusf(float x) {
    return x > 20.f ? x : log1pf(expf(x));
}

// ---------- launch 1: degree ----------
__global__ void k_deg(const int* __restrict__ ei, const float* __restrict__ ew, int E) {
    int i = blockIdx.x * blockDim.x + threadIdx.x;
    if (i < E)           atomicAdd(&g_deg[ei[E + i]], ew[i]);
    else if (i < E + NN) atomicAdd(&g_deg[i - E], 1.f);
}

// ---------- launch 2: normalized adjacency ----------
__global__ void k_nmat(const int* __restrict__ ei, const float* __restrict__ ew, int E) {
    int i = blockIdx.x * blockDim.x + threadIdx.x;
    if (i < E) {
        int s = ei[i], d = ei[E + i];
        float nm = ew[i] * rsqrtf(fmaxf(g_deg[s], 1e-12f)) * rsqrtf(fmaxf(g_deg[d], 1e-12f));
        int bb = d / VG;
        g_Nm[bb * 361 + (d - bb * VG) * VG + (s - bb * VG)] = nm;
    } else if (i < E + NN) {
        int vv = i - E;
        float r = rsqrtf(fmaxf(g_deg[vv], 1e-12f));
        g_Nm[(vv / VG) * 361 + (vv % VG) * VG + (vv % VG)] = r * r;
    }
}

// ---------- launch 3: fused projections + ub precompute ----------
// 128 blocks = (b, t-chunk of 64). Weights loaded ONCE per block, loop 64 t's.
#define O2_IPW 0        /* ipwT[k*128+e] 4096 */
#define O2_GBW 4096     /* gBwT[k*64+e]  4096 */
#define O2_XPW 8192     /* xpws[d*36+j]  2304 */
#define O2_NM  10496    /* nm 364 */
#define O2_DTW 10860    /* dtwS 128: dtwS[r*64+e] = dtw[e*2+r] */
#define O2_DTB 10988    /* 64 */
#define O2_BB  11052    /* 64 */
#define O2_XS  11116    /* 608 */
#define O2_US  11724    /* 1216 */
#define O2_UA  12940    /* 1216 */
#define O2_DTR 14156    /* 40 */
#define SMTOT2 14196

__global__ void __launch_bounds__(NTH, 1) k_preub(
    const float* __restrict__ x_in, const float* __restrict__ ipw,
    const float* __restrict__ xpw,  const float* __restrict__ dtw,
    const float* __restrict__ dtb,  const float* __restrict__ gBw,
    const float* __restrict__ gBb)
{
    extern __shared__ __align__(16) float sp[];
    float* ipwT = sp + O2_IPW;
    float* gBwT = sp + O2_GBW;
    float* xpws = sp + O2_XPW;
    float* nm   = sp + O2_NM;
    float* dtwS = sp + O2_DTW;
    float* dtbS = sp + O2_DTB;
    float* bBs  = sp + O2_BB;
    float* xs   = sp + O2_XS;
    float* us   = sp + O2_US;
    float* uaS  = sp + O2_UA;
    float* dtr  = sp + O2_DTR;

    const int tid = threadIdx.x;
    const int b = blockIdx.x >> 2, tg = blockIdx.x & 3;
    const int v = tid >> 5, l = tid & 31;
    const int node = b * VG + v;

    for (int i = tid; i < 4096; i += NTH) ipwT[(i & 31) * 128 + (i >> 5)] = ipw[i];
    for (int i = tid; i < 4096; i += NTH) gBwT[(i & 63) * 64 + (i >> 6)] = gBw[i];
    for (int i = tid; i < 2176; i += NTH) { int j = i >> 6, d = i & 63; xpws[d * 36 + j] = xpw[i]; }
    for (int i = tid; i < 361; i += NTH) nm[i] = g_Nm[b * 361 + i];
    if (tid < 128) dtwS[(tid & 1) * 64 + (tid >> 1)] = dtw[tid];
    if (tid < 64)  { dtbS[tid] = dtb[tid]; bBs[tid] = gBb[tid]; }
    __syncthreads();

    for (int tt = 0; tt < 64; ++tt) {
        int t = tg * 64 + tt;
        xs[tid] = x_in[node * 8192 + t * 32 + l];
        __syncthreads();

        // u, z
        float u0 = 0, u1 = 0, z0 = 0, z1 = 0;
        #pragma unroll 8
        for (int k = 0; k < 32; ++k) {
            float xk = xs[v * 32 + k];
            u0 = fmaf(ipwT[k * 128 + l], xk, u0);
            u1 = fmaf(ipwT[k * 128 + 32 + l], xk, u1);
            z0 = fmaf(ipwT[k * 128 + 64 + l], xk, z0);
            z1 = fmaf(ipwT[k * 128 + 96 + l], xk, z1);
        }
        us[v * 64 + l] = u0; us[v * 64 + 32 + l] = u1;
        int gb = t * ROW + node * 64;
        g_u[gb + l] = u0; g_u[gb + 32 + l] = u1;
        g_z[gb + l] = z0; g_z[gb + 32 + l] = z1;
        __syncthreads();

        // x_dbl (646 tasks) + ua = Nm @ u
        for (int idx = tid; idx < 646; idx += NTH) {
            int vv = idx / 34, j = idx - vv * 34;
            float a = 0.f;
            #pragma unroll 8
            for (int d = 0; d < 64; ++d) a = fmaf(xpws[d * 36 + j], us[vv * 64 + d], a);
            if (j < 2)       dtr[vv * 2 + j] = a;
            else if (j < 18) g_B[t * BCR + (b * VG + vv) * 16 + (j - 2)] = a;
            else             g_C[t * BCR + (b * VG + vv) * 16 + (j - 18)] = a;
        }
        {
            float a0 = 0, a1 = 0;
            #pragma unroll
            for (int vp = 0; vp < VG; ++vp) {
                float n = nm[v * VG + vp];
                a0 = fmaf(n, us[vp * 64 + l], a0);
                a1 = fmaf(n, us[vp * 64 + 32 + l], a1);
            }
            uaS[v * 64 + l] = a0; uaS[v * 64 + 32 + l] = a1;
        }
        __syncthreads();

        // dt + G = (gBw @ ua + bB) * dt
        float r0 = dtr[v * 2], r1 = dtr[v * 2 + 1];
        float d0 = softplusf(fmaf(r0, dtwS[l], fmaf(r1, dtwS[64 + l], dtbS[l])));
        float d1 = softplusf(fmaf(r0, dtwS[32 + l], fmaf(r1, dtwS[96 + l], dtbS[32 + l])));
        g_dt[gb + l] = d0; g_dt[gb + 32 + l] = d1;

        float gg0 = bBs[l], gg1 = bBs[l + 32];
        #pragma unroll 8
        for (int k = 0; k < 64; ++k) {
            float ua0 = uaS[v * 64 + k];
            gg0 = fmaf(gBwT[k * 64 + l], ua0, gg0);
            gg1 = fmaf(gBwT[k * 64 + 32 + l], ua0, gg1);
        }
        g_G[gb + l] = gg0 * d0; g_G[gb + 32 + l] = gg1 * d1;
        __syncthreads();
    }
}

// ---------- launch 4: scan, persistent, 128 CTAs (R8 structure) ----------
#define O_WA  0
#define O_WC  4096
#define O_NM  8192
#define O_S   8576
#define O_Q   13440
#define O_R   18304
#define O_QC  23168
#define O_CSV 24384
#define O_BS  24404
#define O_CS  24480
#define O_BA  24556
#define O_BC  24620
#define SMTOT 24684

__global__ void __launch_bounds__(NTH, 1) k_scan(
    const float* __restrict__ A_log,
    const float* __restrict__ gAw, const float* __restrict__ gAb,
    const float* __restrict__ gCw, const float* __restrict__ gCb)
{
    extern __shared__ __align__(16) float sm[];
    float* WAe = sm + O_WA;   float* WCe = sm + O_WC;
    float* NMs = sm + O_NM;   float* QCs = sm + O_QC;
    float* CSVs = sm + O_CSV; float* bAs = sm + O_BA;
    float4* S4 = (float4*)(sm + O_S);
    float4* Q4 = (float4*)(sm + O_Q);
    float4* R4 = (float4*)(sm + O_R);
    float4* BS4 = (float4*)(sm + O_BS);
    float4* CS4 = (float4*)(sm + O_CS);
    const float4* WAe4 = (const float4*)WAe;
    const float4* WCe4 = (const float4*)WCe;
    const float4* bC4  = (const float4*)(sm + O_BC);

    const int tid = threadIdx.x;
    const int b = blockIdx.x >> 2, g = blockIdx.x & 3;
    const int v = tid >> 5, e0 = tid & 31, e1 = e0 + 32;   // E-phase mapping
    const int ae = tid & 63, agrp = tid >> 6;              // Agg mapping (agrp 0..9)
    const int av0 = agrp * 2, av1 = av0 + 1;               // agrp==9 -> v=18 (2 e-slots)

    for (int i = tid; i < 4096; i += NTH) {
        WAe[i] = gAw[(i & 63) * 64 + (i >> 6)];
        WCe[i] = gCw[(i & 63) * 64 + (i >> 6)];
    }
    for (int i = tid; i < 361; i += NTH) NMs[i] = g_Nm[b * 361 + i];
    for (int i = tid; i < 4864; i += NTH) sm[O_R + i] = 0.f;
    if (tid < 64) { bAs[tid] = gAb[tid]; sm[O_BC + tid] = gCb[tid]; }

    float Ax0 = -__expf(A_log[e0 * 16 + g * 4 + 0]);
    float Ay0 = -__expf(A_log[e0 * 16 + g * 4 + 1]);
    float Az0 = -__expf(A_log[e0 * 16 + g * 4 + 2]);
    float Aw0 = -__expf(A_log[e0 * 16 + g * 4 + 3]);
    float Ax1 = -__expf(A_log[e1 * 16 + g * 4 + 0]);
    float Ay1 = -__expf(A_log[e1 * 16 + g * 4 + 1]);
    float Az1 = -__expf(A_log[e1 * 16 + g * 4 + 2]);
    float Aw1 = -__expf(A_log[e1 * 16 + g * 4 + 3]);

    int gb0 = b * 1216 + (v << 6) + e0;
    float pdt0 = g_dt[gb0], pdt1 = g_dt[gb0 + 32];
    float pg0  = g_G[gb0],  pg1  = g_G[gb0 + 32];
    if (tid < VG) {
        int bcb = (b * VG + tid) * 16 + (g << 2);
        BS4[tid] = *(const float4*)&g_B[bcb];
        CS4[tid] = *(const float4*)&g_C[bcb];
    }
    float* yout = g_yp + (size_t)g * YPG;
    __syncthreads();

    for (int t = 0; t < LS; ++t) {
        // ---- E: S = (R + bA)*exp(dt*A) + G*B ----
        {
            float4 b4 = BS4[v];
            float ba0 = bAs[e0], ba1 = bAs[e1];
            float4 r = R4[(v << 6) + e0], s;
            s.x = fmaf(r.x + ba0, __expf(pdt0 * Ax0), pg0 * b4.x);
            s.y = fmaf(r.y + ba0, __expf(pdt0 * Ay0), pg0 * b4.y);
            s.z = fmaf(r.z + ba0, __expf(pdt0 * Az0), pg0 * b4.z);
            s.w = fmaf(r.w + ba0, __expf(pdt0 * Aw0), pg0 * b4.w);
            S4[(v << 6) + e0] = s;
            r = R4[(v << 6) + e1];
            s.x = fmaf(r.x + ba1, __expf(pdt1 * Ax1), pg1 * b4.x);
            s.y = fmaf(r.y + ba1, __expf(pdt1 * Ay1), pg1 * b4.y);
            s.z = fmaf(r.z + ba1, __expf(pdt1 * Az1), pg1 * b4.z);
            s.w = fmaf(r.w + ba1, __expf(pdt1 * Aw1), pg1 * b4.w);
            S4[(v << 6) + e1] = s;
        }
        __syncthreads();

        // ---- Agg (v-paired): Q = Nm*S ; QC = Q.C ; CSV ----
        {
            if (agrp < 9) {
                float4 q0 = {0,0,0,0}, q1 = {0,0,0,0};
                const float* nrow0 = NMs + av0 * VG;
                const float* nrow1 = NMs + av1 * VG;
                #pragma unroll
                for (int vp = 0; vp < VG; ++vp) {
                    float4 s4 = S4[(vp << 6) + ae];
                    float n0 = nrow0[vp], n1 = nrow1[vp];
                    q0.x = fmaf(n0, s4.x, q0.x); q0.y = fmaf(n0, s4.y, q0.y);
                    q0.z = fmaf(n0, s4.z, q0.z); q0.w = fmaf(n0, s4.w, q0.w);
                    q1.x = fmaf(n1, s4.x, q1.x); q1.y = fmaf(n1, s4.y, q1.y);
                    q1.z = fmaf(n1, s4.z, q1.z); q1.w = fmaf(n1, s4.w, q1.w);
                }
                Q4[(av0 << 6) + ae] = q0;
                Q4[(av1 << 6) + ae] = q1;
                float4 c0 = CS4[av0], c1 = CS4[av1];
                QCs[(av0 << 6) + ae] = q0.x*c0.x + q0.y*c0.y + q0.z*c0.z + q0.w*c0.w;
                QCs[(av1 << 6) + ae] = q1.x*c1.x + q1.y*c1.y + q1.z*c1.z + q1.w*c1.w;
            } else {
                const float* nrow0 = NMs + 18 * VG;
                float4 c0 = CS4[18];
                #pragma unroll
                for (int h = 0; h < 2; ++h) {
                    int aeh = ae + h * 32;   // ae in 0..31 here
                    float4 q0 = {0,0,0,0};
                    #pragma unroll
                    for (int vp = 0; vp < VG; ++vp) {
                        float4 s4 = S4[(vp << 6) + aeh];
                        float n0 = nrow0[vp];
                        q0.x = fmaf(n0, s4.x, q0.x); q0.y = fmaf(n0, s4.y, q0.y);
                        q0.z = fmaf(n0, s4.z, q0.z); q0.w = fmaf(n0, s4.w, q0.w);
                    }
                    Q4[(18 << 6) + aeh] = q0;
                    QCs[(18 << 6) + aeh] = q0.x*c0.x + q0.y*c0.y + q0.z*c0.z + q0.w*c0.w;
                }
            }
            if (tid < VG) { float4 cc = CS4[tid]; CSVs[tid] = cc.x + cc.y + cc.z + cc.w; }
        }
        __syncthreads();

        // ---- GEMM: R(t+1)=WA@Q (304 thr) || y(t)=WC@QC + bC*CSV (304 thr); prefetch t+1 ----
        {
            int tn = (t + 1 < LS) ? t + 1 : t;
            if (tid < VG) {
                int bcb = tn * BCR + (b * VG + tid) * 16 + (g << 2);
                BS4[tid] = *(const float4*)&g_B[bcb];
                CS4[tid] = *(const float4*)&g_C[bcb];
            }
            int gbase = tn * ROW + b * 1216 + (v << 6) + e0;
            float ndt0 = g_dt[gbase], ndt1 = g_dt[gbase + 32];
            float ng0  = g_G[gbase],  ng1  = g_G[gbase + 32];

            if (tid < 304) {
                int tv = tid >> 4, eq = tid & 15;
                float4 a0 = {0,0,0,0}, a1 = a0, a2 = a0, a3 = a0;
                #pragma unroll 8
                for (int k = 0; k < 64; ++k) {
                    float4 w = WAe4[(k << 4) + eq];
                    float4 q = Q4[(tv << 6) + k];
                    a0.x = fmaf(w.x, q.x, a0.x); a0.y = fmaf(w.x, q.y, a0.y);
                    a0.z = fmaf(w.x, q.z, a0.z); a0.w = fmaf(w.x, q.w, a0.w);
                    a1.x = fmaf(w.y, q.x, a1.x); a1.y = fmaf(w.y, q.y, a1.y);
                    a1.z = fmaf(w.y, q.z, a1.z); a1.w = fmaf(w.y, q.w, a1.w);
                    a2.x = fmaf(w.z, q.x, a2.x); a2.y = fmaf(w.z, q.y, a2.y);
                    a2.z = fmaf(w.z, q.z, a2.z); a2.w = fmaf(w.z, q.w, a2.w);
                    a3.x = fmaf(w.w, q.x, a3.x); a3.y = fmaf(w.w, q.y, a3.y);
                    a3.z = fmaf(w.w, q.z, a3.z); a3.w = fmaf(w.w, q.w, a3.w);
                }
                int rb = (tv << 6) + (eq << 2);
                R4[rb]     = a0;
                R4[rb + 1] = a1;
                R4[rb + 2] = a2;
                R4[rb + 3] = a3;
            } else {
                int yt = tid - 304;
                int tv = yt >> 4, eq = yt & 15;
                float csv = CSVs[tv];
                float4 bc = bC4[eq];
                float4 acc = make_float4(bc.x * csv, bc.y * csv, bc.z * csv, bc.w * csv);
                #pragma unroll 8
                for (int k = 0; k < 64; ++k) {
                    float qc = QCs[(tv << 6) + k];
                    float4 w = WCe4[(k << 4) + eq];
                    acc.x = fmaf(w.x, qc, acc.x); acc.y = fmaf(w.y, qc, acc.y);
                    acc.z = fmaf(w.z, qc, acc.z); acc.w = fmaf(w.w, qc, acc.w);
                }
                *(float4*)(yout + (size_t)t * ROW + (b * VG + tv) * 64 + (eq << 2)) = acc;
            }
            pdt0 = ndt0; pdt1 = ndt1; pg0 = ng0; pg1 = ng1;
        }
        __syncthreads();
    }
}

// ---------- launch 5: post + deg re-zero. 608 blocks (one per node), 64 iters ----------
__global__ void __launch_bounds__(256) k_post(
    const float* __restrict__ Dp, const float* __restrict__ opw, float* __restrict__ out)
{
    __shared__ float ys[256];
    __shared__ float opws[2048];   // opw[o][e] -> opws[e*32+o]
    int tid = threadIdx.x;
    int node = blockIdx.x;
    if (node < 3) { int i = node * 256 + tid; if (i < NN) g_deg[i] = 0.f; }
    for (int i = tid; i < 2048; i += 256) { int o = i >> 6, e = i & 63; opws[e * 32 + o] = opw[i]; }
    int sub = tid >> 6, e = tid & 63;
    float de = Dp[e];
    __syncthreads();

    for (int tt = 0; tt < 64; ++tt) {
        int t = tt * 4 + sub;
        int ib = t * ROW + node * 64 + e;
        float y = g_yp[ib] + g_yp[YPG + ib] + g_yp[2 * YPG + ib] + g_yp[3 * YPG + ib];
        y = fmaf(de, g_u[ib], y);
        float z = g_z[ib];
        y *= z / (1.f + expf(-z));
        ys[sub * 64 + e] = y;
        __syncthreads();
        if (e < 32) {
            float a = 0.f;
            #pragma unroll 8
            for (int k = 0; k < 64; ++k) a = fmaf(opws[k * 32 + e], ys[sub * 64 + k], a);
            out[(node * 256 + t) * 32 + e] = a;
        }
        __syncthreads();
    }
}

extern "C" void kernel_launch(void* const* d_in, const int* in_sizes, int n_in,
                              void* d_out, int out_size) {
    const float* x_in = (const float*)d_in[0];
    const int*   ei   = (const int*)  d_in[1];
    const float* ew   = (const float*)d_in[2];
    const float* ipw  = (const float*)d_in[3];
    const float* xpw  = (const float*)d_in[4];
    const float* dtw  = (const float*)d_in[5];
    const float* dtb  = (const float*)d_in[6];
    const float* Alog = (const float*)d_in[7];
    const float* Dp   = (const float*)d_in[8];
    const float* opw  = (const float*)d_in[9];
    const float* gAw  = (const float*)d_in[10];
    const float* gAb  = (const float*)d_in[11];
    const float* gBw  = (const float*)d_in[12];
    const float* gBb  = (const float*)d_in[13];
    const float* gCw  = (const float*)d_in[14];
    const float* gCb  = (const float*)d_in[15];
    float* out = (float*)d_out;
    int E = in_sizes[1] / 2;

    static int smem_set = 0;
    if (!smem_set) {
        cudaFuncSetAttribute(k_scan,  cudaFuncAttributeMaxDynamicSharedMemorySize, SMTOT * 4);
        cudaFuncSetAttribute(k_preub, cudaFuncAttributeMaxDynamicSharedMemorySize, SMTOT2 * 4);
        smem_set = 1;
    }

    k_deg  <<<(E + NN + 255) / 256, 256>>>(ei, ew, E);
    k_nmat <<<(E + NN + 255) / 256, 256>>>(ei, ew, E);
    k_preub<<<128, NTH, SMTOT2 * 4>>>(x_in, ipw, xpw, dtw, dtb, gBw, gBb);
    k_scan <<<128, NTH, SMTOT * 4>>>(Alog, gAw, gAb, gCw, gCb);
    k_post <<<NN, 256>>>(Dp, opw, out);
}